// round 15
// baseline (speedup 1.0000x reference)
#include <cuda_runtime.h>
#include <cuda_bf16.h>
#include <cstdint>

#define N_TOK 4096
#define HEPS 1e-6f
#define NCHUNK 64

// ---------------- scratch (device globals; no allocs allowed) ----------------
__device__ __align__(16) __nv_bfloat16 g_wq_hi[256*256];
__device__ __align__(16) __nv_bfloat16 g_wq_lo[256*256];
__device__ __align__(16) __nv_bfloat16 g_wk_hi[256*256];
__device__ __align__(16) __nv_bfloat16 g_wk_lo[256*256];
__device__ __align__(16) __nv_bfloat16 g_xt_hi[4096*256];   // x transposed [n][c]
__device__ __align__(16) __nv_bfloat16 g_xt_lo[4096*256];
// positive heads only; heads 4..7 are reciprocals computed on the fly
__device__ __align__(16) float g_qf[4*64*N_TOK];   // [h][e][n] = exp(+h)
__device__ __align__(16) float g_kf[4*64*N_TOK];
__device__ __align__(16) float g_vf[4*64*N_TOK];
__device__ __align__(16) float g_v [256*N_TOK];
__device__ __align__(16) float g_pKV[8*NCHUNK*64*64];
__device__ __align__(16) float g_pS [8*NCHUNK*64];
__device__ __align__(16) float g_KV[8*64*64];
__device__ __align__(16) float g_S [8*64];

// ==================== helpers ================================================
__device__ __forceinline__ uint32_t smem_u32(const void* p) {
    uint32_t a;
    asm("{ .reg .u64 tmp; cvta.to.shared.u64 tmp, %1; cvt.u32.u64 %0, tmp; }"
        : "=r"(a) : "l"(p));
    return a;
}
__device__ __forceinline__ void ldm_x4(uint32_t addr, uint32_t& r0, uint32_t& r1,
                                       uint32_t& r2, uint32_t& r3) {
    asm volatile("ldmatrix.sync.aligned.m8n8.x4.shared.b16 {%0,%1,%2,%3}, [%4];"
                 : "=r"(r0), "=r"(r1), "=r"(r2), "=r"(r3) : "r"(addr));
}
__device__ __forceinline__ void mma_bf16(float* c, const uint32_t* a,
                                         const uint32_t* b) {
    asm volatile(
        "mma.sync.aligned.m16n8k16.row.col.f32.bf16.bf16.f32 "
        "{%0,%1,%2,%3}, {%4,%5,%6,%7}, {%8,%9}, {%0,%1,%2,%3};"
        : "+f"(c[0]), "+f"(c[1]), "+f"(c[2]), "+f"(c[3])
        : "r"(a[0]), "r"(a[1]), "r"(a[2]), "r"(a[3]), "r"(b[0]), "r"(b[1]));
}
__device__ __forceinline__ void cp16(uint32_t s, const void* g) {
    asm volatile("cp.async.cg.shared.global [%0], [%1], 16;" :: "r"(s), "l"(g));
}
#define CP_COMMIT() asm volatile("cp.async.commit_group;" ::: "memory")
#define CP_WAIT1()  asm volatile("cp.async.wait_group 1;"  ::: "memory")
#define CP_WAIT0()  asm volatile("cp.async.wait_group 0;"  ::: "memory")
__device__ __forceinline__ float rcpf(float x) {
    float r;
    asm("rcp.approx.f32 %0, %1;" : "=f"(r) : "f"(x));
    return r;
}
__device__ __forceinline__ float4 rcp4(float4 v) {
    return make_float4(rcpf(v.x), rcpf(v.y), rcpf(v.z), rcpf(v.w));
}

// ---------------- K0: fused prep — Weff split (blocks 0..511) + x transpose --
__global__ void __launch_bounds__(256) k_prep(
        const float* __restrict__ Wq, const float* __restrict__ Wk,
        const float* __restrict__ Wmq, const float* __restrict__ Wmk,
        const float* __restrict__ x2) {
    __shared__ float sWm[64];
    __shared__ float sx[32][33];
    int b = blockIdx.x;
    int t = threadIdx.x;
    if (b < 512) {
        int o = b & 255, y = b >> 8;
        int h = o >> 6, e = o & 63;
        const float* Wm = y ? Wmk : Wmq;
        const float* Wb = y ? Wk  : Wq;
        if (t < 64) sWm[t] = Wm[e*64 + t];
        __syncthreads();
        float acc = 0.f;
        #pragma unroll 8
        for (int d = 0; d < 64; d++)
            acc += sWm[d] * Wb[(h*64 + d)*256 + t];
        __nv_bfloat16 hi = __float2bfloat16(acc);
        __nv_bfloat16 lo = __float2bfloat16(acc - __bfloat162float(hi));
        if (y) { g_wk_hi[o*256 + t] = hi; g_wk_lo[o*256 + t] = lo; }
        else   { g_wq_hi[o*256 + t] = hi; g_wq_lo[o*256 + t] = lo; }
    } else {
        int bb = b - 512;              // 0..1023
        int c0 = (bb >> 7) * 32;       // 8 slabs
        int n0 = (bb & 127) * 32;      // 128 slabs
        int tx = t & 31, ty = t >> 5;  // 32 x 8
        #pragma unroll
        for (int i = 0; i < 4; i++)
            sx[ty + 8*i][tx] = x2[(c0 + ty + 8*i)*N_TOK + n0 + tx];
        __syncthreads();
        #pragma unroll
        for (int i = 0; i < 4; i++) {
            int n = n0 + ty + 8*i;
            float v = sx[tx][ty + 8*i];
            __nv_bfloat16 hi = __float2bfloat16(v);
            __nv_bfloat16 lo = __float2bfloat16(v - __bfloat162float(hi));
            g_xt_hi[n*256 + c0 + tx] = hi;
            g_xt_lo[n*256 + c0 + tx] = lo;
        }
    }
}

// ---------------- K1: hedgehog GEMM via mma.sync bf16, cp.async 2-stage ------
#define APITCH 24
__global__ void __launch_bounds__(256, 2)
k1mma(const float* __restrict__ bmq, const float* __restrict__ bmk) {
    __shared__ __nv_bfloat16 Ah[2][128][APITCH], Al[2][128][APITCH];
    __shared__ __nv_bfloat16 Bh[2][64][APITCH],  Bl[2][64][APITCH];

    int t = threadIdx.x;           // 256
    int lane = t & 31, wid = t >> 5;
    int wm = wid >> 1, wn = wid & 1;
    int m0 = blockIdx.x * 128;     // 2 M-tiles
    int n0 = blockIdx.y * 64;      // 64 N-tiles
    int z  = blockIdx.z;           // q / k
    const __nv_bfloat16* gAh = z ? g_wk_hi : g_wq_hi;
    const __nv_bfloat16* gAl = z ? g_wk_lo : g_wq_lo;
    const float* bm = z ? bmk : bmq;
    float* f        = z ? g_kf : g_qf;

    float acc[2][4][4] = {};       // [mtile][ntile][reg]

    int a_row = (lane & 15), a_col = (lane >> 4) * 8;
    int b_row = (lane >> 4) * 8 + (lane & 7), b_col = ((lane >> 3) & 1) * 8;

    int r  = t >> 1, cc = (t & 1) * 8;          // A: 128 rows x 16 cols
    int rb = (t < 128) ? r : 0;                 // clamp: B pointers stay in-bounds
    const __nv_bfloat16* pAh = &gAh[(m0 + r)*256 + cc];
    const __nv_bfloat16* pAl = &gAl[(m0 + r)*256 + cc];
    const __nv_bfloat16* pBh = &g_xt_hi[(n0 + rb)*256 + cc];
    const __nv_bfloat16* pBl = &g_xt_lo[(n0 + rb)*256 + cc];

    {   // prefetch stage 0
        cp16(smem_u32(&Ah[0][r][cc]), pAh);
        cp16(smem_u32(&Al[0][r][cc]), pAl);
        if (t < 128) {
            cp16(smem_u32(&Bh[0][rb][cc]), pBh);
            cp16(smem_u32(&Bl[0][rb][cc]), pBl);
        }
        CP_COMMIT();
    }

    for (int ks = 0; ks < 16; ks++) {
        if (ks < 15) {
            int s = (ks + 1) & 1, k0 = (ks + 1) * 16;
            cp16(smem_u32(&Ah[s][r][cc]), pAh + k0);
            cp16(smem_u32(&Al[s][r][cc]), pAl + k0);
            if (t < 128) {
                cp16(smem_u32(&Bh[s][rb][cc]), pBh + k0);
                cp16(smem_u32(&Bl[s][rb][cc]), pBl + k0);
            }
            CP_COMMIT();
            CP_WAIT1();
        } else {
            CP_WAIT0();
        }
        __syncthreads();
        int s = ks & 1;

        uint32_t ah[2][4], al[2][4], bh[4][2], bl[4][2];
        #pragma unroll
        for (int mt = 0; mt < 2; mt++) {
            uint32_t ad = smem_u32(&Ah[s][wm*32 + mt*16 + a_row][a_col]);
            ldm_x4(ad, ah[mt][0], ah[mt][1], ah[mt][2], ah[mt][3]);
            uint32_t ad2 = smem_u32(&Al[s][wm*32 + mt*16 + a_row][a_col]);
            ldm_x4(ad2, al[mt][0], al[mt][1], al[mt][2], al[mt][3]);
        }
        #pragma unroll
        for (int np = 0; np < 2; np++) {
            uint32_t bd = smem_u32(&Bh[s][wn*32 + np*16 + b_row][b_col]);
            ldm_x4(bd, bh[np*2][0], bh[np*2][1], bh[np*2+1][0], bh[np*2+1][1]);
            uint32_t bd2 = smem_u32(&Bl[s][wn*32 + np*16 + b_row][b_col]);
            ldm_x4(bd2, bl[np*2][0], bl[np*2][1], bl[np*2+1][0], bl[np*2+1][1]);
        }
        #pragma unroll
        for (int mt = 0; mt < 2; mt++)
            #pragma unroll
            for (int nt = 0; nt < 4; nt++) {
                mma_bf16(acc[mt][nt], ah[mt], bh[nt]);
                mma_bf16(acc[mt][nt], ah[mt], bl[nt]);
                mma_bf16(acc[mt][nt], al[mt], bh[nt]);
            }
        __syncthreads();
    }

    // epilogue: bias + exp(+h) only (negative heads are reciprocals, on the fly)
    int qr = lane >> 2, qc = (lane & 3) * 2;
    #pragma unroll
    for (int mt = 0; mt < 2; mt++) {
        int ob = m0 + wm*32 + mt*16;
        int o0 = ob + qr, o1 = ob + qr + 8;
        float b0 = bm[o0 & 63], b1 = bm[o1 & 63];
        #pragma unroll
        for (int nt = 0; nt < 4; nt++) {
            int n = n0 + wn*32 + nt*8 + qc;
            float h00 = acc[mt][nt][0] + b0, h01 = acc[mt][nt][1] + b0;
            float h10 = acc[mt][nt][2] + b1, h11 = acc[mt][nt][3] + b1;
            float2 p0 = {__expf(h00), __expf(h01)};
            float2 p1 = {__expf(h10), __expf(h11)};
            *(float2*)&f[(size_t)o0*N_TOK + n] = p0;
            *(float2*)&f[(size_t)o1*N_TOK + n] = p1;
        }
    }
}

// ---------------- K2a: depthwise 3x3x3 conv, plane-major, LDS-minimized ------
#define CV_PD 19
#define CV_PP 342          // 18*19 plane pitch
__global__ void __launch_bounds__(256) k_conv(const float* __restrict__ x,
                                              const float* __restrict__ Wv,
                                              const float* __restrict__ bv) {
    __shared__ float sx[6*CV_PP]; // 2052 floats
    __shared__ float sw[27];
    int c  = blockIdx.x;           // 256
    int hs = blockIdx.y;           // 4
    int t  = threadIdx.x;          // 256
    int ww = t >> 4, dd = t & 15;

    for (int i = t; i < 6*CV_PP; i += 256) sx[i] = 0.f;
    if (t < 27) sw[t] = Wv[c*27 + t];
    __syncthreads();
    #pragma unroll
    for (int p = 0; p < 6; p++) {
        int hz = hs*4 - 1 + p;
        if (hz >= 0 && hz < 16)
            sx[p*CV_PP + (ww+1)*CV_PD + dd + 1] = x[c*4096 + hz*256 + ww*16 + dd];
    }
    __syncthreads();

    float bias = bv[c];
    float acc[4] = {bias, bias, bias, bias};
    #pragma unroll
    for (int p = 0; p < 6; p++) {
        #pragma unroll
        for (int b = 0; b < 3; b++) {
            const float* row = &sx[p*CV_PP + (ww + b)*CV_PD + dd];
            float r0 = row[0], r1 = row[1], r2 = row[2];
            #pragma unroll
            for (int a = 0; a < 3; a++) {
                int hh = p - a;            // plane p feeds output row hh with tap a
                if (hh >= 0 && hh < 4)     // compile-time resolved
                    acc[hh] += sw[a*9 + b*3 + 0]*r0 + sw[a*9 + b*3 + 1]*r1
                             + sw[a*9 + b*3 + 2]*r2;
            }
        }
    }
    #pragma unroll
    for (int hh = 0; hh < 4; hh++)
        g_v[c*N_TOK + (hs*4 + hh)*256 + ww*16 + dd] = acc[hh];
}

// ---------------- K2b: per-head v mix + exp(+) (128 thr, 4x4, 32n tiles) -----
__global__ void __launch_bounds__(128) k_vmix(const float* __restrict__ Wmv,
                                              const float* __restrict__ bmv) {
    __shared__ float As[16][68];   // Wmv^T staged: [d][e]
    __shared__ float Bs[16][32];   // v: [d][n]
    int h  = blockIdx.x;           // 4
    int n0 = blockIdx.y * 32;      // 128 tiles
    int t  = threadIdx.x;          // 128
    int tx = t & 7, ty = t >> 3;   // 8(n) x 16(e)

    float acc[4][4] = {};

    for (int k0 = 0; k0 < 64; k0 += 16) {
        #pragma unroll
        for (int i = 0; i < 2; i++) {            // A: 64(e) x 16(d)
            int j = t + 128*i;
            int lm = j >> 2, lk = (j & 3) * 4;
            float4 av = *(const float4*)&Wmv[lm*64 + k0 + lk];
            As[lk+0][lm] = av.x; As[lk+1][lm] = av.y;
            As[lk+2][lm] = av.z; As[lk+3][lm] = av.w;
        }
        {                                         // B: 16(d) x 32(n)
            int bk = t >> 3, bn = (t & 7) * 4;
            *(float4*)&Bs[bk][bn] = *(const float4*)&g_v[(h*64 + k0 + bk)*N_TOK + n0 + bn];
        }
        __syncthreads();
        #pragma unroll
        for (int kk = 0; kk < 16; kk++) {
            float a[4], b[4];
            *(float4*)&a[0] = *(const float4*)&As[kk][ty*4];
            *(float4*)&b[0] = *(const float4*)&Bs[kk][tx*4];
            #pragma unroll
            for (int i = 0; i < 4; i++)
                #pragma unroll
                for (int j = 0; j < 4; j++)
                    acc[i][j] += a[i] * b[j];
        }
        __syncthreads();
    }

    int n = n0 + tx*4;
    #pragma unroll
    for (int i = 0; i < 4; i++) {
        int e = ty*4 + i;
        float bias = bmv[e];
        float h0 = acc[i][0] + bias, h1 = acc[i][1] + bias;
        float h2 = acc[i][2] + bias, h3 = acc[i][3] + bias;
        float4 p = {__expf(h0), __expf(h1), __expf(h2), __expf(h3)};
        *(float4*)&g_vf[(h*64 + e)*N_TOK + n] = p;
    }
}

// ---------------- K3b: partial KV + partial S over 64-token chunks -----------
__global__ void __launch_bounds__(128) k_pkv() {
    __shared__ float skt[16][68];  // kf transposed: [nn][e]
    __shared__ float svt[16][68];  // vf transposed: [nn][d]
    int h = blockIdx.x, chunk = blockIdx.y;
    int hb = h & 3;
    bool neg = h >= 4;
    int t = threadIdx.x;           // 128
    int tx = t & 15, ty = t >> 4;
    int base_n = chunk * 64;

    float acc[8][4] = {};
    float s[2] = {};

    for (int sub = 0; sub < 4; sub++) {
        int n0 = base_n + sub * 16;
        #pragma unroll
        for (int i = 0; i < 2; i++) {
            int j = t + 128*i;
            int e = j >> 2, nf = (j & 3) * 4;
            float4 kq = *(const float4*)&g_kf[(hb*64 + e)*N_TOK + n0 + nf];
            if (neg) kq = rcp4(kq);
            skt[nf+0][e] = kq.x; skt[nf+1][e] = kq.y;
            skt[nf+2][e] = kq.z; skt[nf+3][e] = kq.w;
            s[i] += (kq.x + kq.y) + (kq.z + kq.w);
            float4 vq = *(const float4*)&g_vf[(hb*64 + e)*N_TOK + n0 + nf];
            if (neg) vq = rcp4(vq);
            svt[nf+0][e] = vq.x; svt[nf+1][e] = vq.y;
            svt[nf+2][e] = vq.z; svt[nf+3][e] = vq.w;
        }
        __syncthreads();
        #pragma unroll
        for (int nn = 0; nn < 16; nn++) {
            float a[8], b[4];
            *(float4*)&a[0] = *(const float4*)&skt[nn][ty*8];
            *(float4*)&a[4] = *(const float4*)&skt[nn][ty*8 + 4];
            *(float4*)&b[0] = *(const float4*)&svt[nn][tx*4];
            #pragma unroll
            for (int i = 0; i < 8; i++)
                #pragma unroll
                for (int j = 0; j < 4; j++)
                    acc[i][j] += a[i] * b[j];
        }
        __syncthreads();
    }

    float* dst = &g_pKV[(h*NCHUNK + chunk)*64*64];
    #pragma unroll
    for (int i = 0; i < 8; i++) {
        float4 c0 = {acc[i][0], acc[i][1], acc[i][2], acc[i][3]};
        *(float4*)&dst[(ty*8 + i)*64 + tx*4] = c0;
    }

    #pragma unroll
    for (int i = 0; i < 2; i++) {
        s[i] += __shfl_down_sync(0xffffffffu, s[i], 2);
        s[i] += __shfl_down_sync(0xffffffffu, s[i], 1);
    }
    if ((t & 3) == 0) {
        g_pS[(h*NCHUNK + chunk)*64 + (t >> 2)]      = s[0];
        g_pS[(h*NCHUNK + chunk)*64 + (t >> 2) + 32] = s[1];
    }
}

// ---------------- K3c: reduce partial KV and partial S -----------------------
__global__ void k_rkv() {
    int h = blockIdx.x;
    int t = threadIdx.x;           // 256
    for (int idx = t; idx < 4096; idx += 256) {
        float acc = 0.f;
        #pragma unroll
        for (int c = 0; c < NCHUNK; c++)
            acc += g_pKV[(h*NCHUNK + c)*4096 + idx];
        g_KV[h*4096 + idx] = acc;
    }
    if (t < 64) {
        float acc = 0.f;
        #pragma unroll
        for (int c = 0; c < NCHUNK; c++)
            acc += g_pS[(h*NCHUNK + c)*64 + t];
        g_S[h*64 + t] = acc;
    }
}

// ---------------- K4: out = (qf . KV) / (qf . S + eps) (4x4, 32n tiles) ------
__global__ void __launch_bounds__(128) k_out(float* __restrict__ out) {
    __shared__ float sKV[64][68];  // [e][d]
    __shared__ float Bs[16][32];   // qf: [e][n]
    __shared__ float sS[64];
    int h  = blockIdx.x;           // 8
    int hb = h & 3;
    bool neg = h >= 4;
    int n0 = blockIdx.y * 32;      // 128 tiles
    int t  = threadIdx.x;          // 128
    int tx = t & 7, ty = t >> 3;   // 8(n) x 16(d)

    #pragma unroll
    for (int i = 0; i < 8; i++) {
        int j = t + 128*i;
        int e = j >> 4, dc = (j & 15) * 4;
        *(float4*)&sKV[e][dc] = *(const float4*)&g_KV[h*4096 + e*64 + dc];
    }
    if (t < 64) sS[t] = g_S[h*64 + t];

    float acc[4][4] = {};
    float dacc[4] = {};

    for (int k0 = 0; k0 < 64; k0 += 16) {
        {
            int bk = t >> 3, bn = (t & 7) * 4;
            float4 qv = *(const float4*)&g_qf[(hb*64 + k0 + bk)*N_TOK + n0 + bn];
            if (neg) qv = rcp4(qv);
            *(float4*)&Bs[bk][bn] = qv;
        }
        __syncthreads();
        #pragma unroll
        for (int kk = 0; kk < 16; kk++) {
            int e = k0 + kk;
            float a[4], b[4];
            *(float4*)&a[0] = *(const float4*)&sKV[e][ty*4];
            *(float4*)&b[0] = *(const float4*)&Bs[kk][tx*4];
            float sv = sS[e];
            #pragma unroll
            for (int j = 0; j < 4; j++) dacc[j] += sv * b[j];
            #pragma unroll
            for (int i = 0; i < 4; i++)
                #pragma unroll
                for (int j = 0; j < 4; j++)
                    acc[i][j] += a[i] * b[j];
        }
        __syncthreads();
    }

    float inv[4];
    #pragma unroll
    for (int j = 0; j < 4; j++) inv[j] = 1.f / (dacc[j] + HEPS);

    int n = n0 + tx*4;
    #pragma unroll
    for (int i = 0; i < 4; i++) {
        int d = ty*4 + i;
        float4 c0 = {acc[i][0]*inv[0], acc[i][1]*inv[1], acc[i][2]*inv[2], acc[i][3]*inv[3]};
        *(float4*)&out[(h*64 + d)*N_TOK + n] = c0;
    }
}

// -----------------------------------------------------------------------------
extern "C" void kernel_launch(void* const* d_in, const int* in_sizes, int n_in,
                              void* d_out, int out_size) {
    const float* x   = (const float*)d_in[0];   // [1,256,16,16,16]
    const float* Wq  = (const float*)d_in[1];   // [256,256]
    const float* Wk  = (const float*)d_in[2];   // [256,256]
    const float* Wv  = (const float*)d_in[3];   // [256,1,3,3,3]
    const float* bv  = (const float*)d_in[4];   // [256]
    const float* Wmq = (const float*)d_in[5];   // [64,64]
    const float* bmq = (const float*)d_in[6];   // [64]
    const float* Wmk = (const float*)d_in[7];   // [64,64]
    const float* bmk = (const float*)d_in[8];   // [64]
    const float* Wmv = (const float*)d_in[9];   // [64,64]
    const float* bmv = (const float*)d_in[10];  // [64]
    float* out = (float*)d_out;                 // [1,512,16,16,16]

    k_prep <<<1536,                256>>>(Wq, Wk, Wmq, Wmk, x);
    k1mma  <<<dim3(2, 64, 2),      256>>>(bmq, bmk);
    k_conv <<<dim3(256, 4),        256>>>(x, Wv, bv);
    k_vmix <<<dim3(4, 128),        128>>>(Wmv, bmv);
    k_pkv  <<<dim3(8, NCHUNK),     128>>>();
    k_rkv  <<<8,                   256>>>();
    k_out  <<<dim3(8, 128),        128>>>(out);
}

// round 16
// speedup vs baseline: 1.3009x; 1.3009x over previous
#include <cuda_runtime.h>
#include <cuda_bf16.h>
#include <cstdint>

#define N_TOK 4096
#define HEPS 1e-6f
#define NCHUNK 32

// ---------------- scratch (device globals; no allocs allowed) ----------------
__device__ __align__(16) __nv_bfloat16 g_wq_hi[256*256];
__device__ __align__(16) __nv_bfloat16 g_wq_lo[256*256];
__device__ __align__(16) __nv_bfloat16 g_wk_hi[256*256];
__device__ __align__(16) __nv_bfloat16 g_wk_lo[256*256];
__device__ __align__(16) __nv_bfloat16 g_xt_hi[4096*256];   // x transposed [n][c]
__device__ __align__(16) __nv_bfloat16 g_xt_lo[4096*256];
// positive heads only; heads 4..7 are reciprocals computed on the fly
__device__ __align__(16) float g_qf[4*64*N_TOK];   // [h][e][n] = exp(+h)
__device__ __align__(16) float g_kf[4*64*N_TOK];
__device__ __align__(16) float g_vf[4*64*N_TOK];
__device__ __align__(16) float g_v [256*N_TOK];
__device__ __align__(16) float g_pKV[8*NCHUNK*64*64];
__device__ __align__(16) float g_pS [8*NCHUNK*64];
__device__ __align__(16) float g_KV[8*64*64];
__device__ __align__(16) float g_S [8*64];

// ==================== helpers ================================================
__device__ __forceinline__ uint32_t smem_u32(const void* p) {
    uint32_t a;
    asm("{ .reg .u64 tmp; cvta.to.shared.u64 tmp, %1; cvt.u32.u64 %0, tmp; }"
        : "=r"(a) : "l"(p));
    return a;
}
__device__ __forceinline__ void ldm_x4(uint32_t addr, uint32_t& r0, uint32_t& r1,
                                       uint32_t& r2, uint32_t& r3) {
    asm volatile("ldmatrix.sync.aligned.m8n8.x4.shared.b16 {%0,%1,%2,%3}, [%4];"
                 : "=r"(r0), "=r"(r1), "=r"(r2), "=r"(r3) : "r"(addr));
}
__device__ __forceinline__ void mma_bf16(float* c, const uint32_t* a,
                                         const uint32_t* b) {
    asm volatile(
        "mma.sync.aligned.m16n8k16.row.col.f32.bf16.bf16.f32 "
        "{%0,%1,%2,%3}, {%4,%5,%6,%7}, {%8,%9}, {%0,%1,%2,%3};"
        : "+f"(c[0]), "+f"(c[1]), "+f"(c[2]), "+f"(c[3])
        : "r"(a[0]), "r"(a[1]), "r"(a[2]), "r"(a[3]), "r"(b[0]), "r"(b[1]));
}
__device__ __forceinline__ void cp16(uint32_t s, const void* g) {
    asm volatile("cp.async.cg.shared.global [%0], [%1], 16;" :: "r"(s), "l"(g));
}
#define CP_COMMIT() asm volatile("cp.async.commit_group;" ::: "memory")
#define CP_WAIT1()  asm volatile("cp.async.wait_group 1;"  ::: "memory")
#define CP_WAIT0()  asm volatile("cp.async.wait_group 0;"  ::: "memory")
__device__ __forceinline__ float rcpf(float x) {
    float r;
    asm("rcp.approx.f32 %0, %1;" : "=f"(r) : "f"(x));
    return r;
}
__device__ __forceinline__ float4 rcp4(float4 v) {
    return make_float4(rcpf(v.x), rcpf(v.y), rcpf(v.z), rcpf(v.w));
}

// ---------------- K0: fused prep — Weff split (blocks 0..511) + x transpose --
__global__ void __launch_bounds__(256) k_prep(
        const float* __restrict__ Wq, const float* __restrict__ Wk,
        const float* __restrict__ Wmq, const float* __restrict__ Wmk,
        const float* __restrict__ x2) {
    __shared__ float sWm[64];
    __shared__ float sx[32][33];
    int b = blockIdx.x;
    int t = threadIdx.x;
    if (b < 512) {
        int o = b & 255, y = b >> 8;
        int h = o >> 6, e = o & 63;
        const float* Wm = y ? Wmk : Wmq;
        const float* Wb = y ? Wk  : Wq;
        if (t < 64) sWm[t] = Wm[e*64 + t];
        __syncthreads();
        float acc = 0.f;
        #pragma unroll 8
        for (int d = 0; d < 64; d++)
            acc += sWm[d] * Wb[(h*64 + d)*256 + t];
        __nv_bfloat16 hi = __float2bfloat16(acc);
        __nv_bfloat16 lo = __float2bfloat16(acc - __bfloat162float(hi));
        if (y) { g_wk_hi[o*256 + t] = hi; g_wk_lo[o*256 + t] = lo; }
        else   { g_wq_hi[o*256 + t] = hi; g_wq_lo[o*256 + t] = lo; }
    } else {
        int bb = b - 512;              // 0..1023
        int c0 = (bb >> 7) * 32;       // 8 slabs
        int n0 = (bb & 127) * 32;      // 128 slabs
        int tx = t & 31, ty = t >> 5;  // 32 x 8
        #pragma unroll
        for (int i = 0; i < 4; i++)
            sx[ty + 8*i][tx] = x2[(c0 + ty + 8*i)*N_TOK + n0 + tx];
        __syncthreads();
        #pragma unroll
        for (int i = 0; i < 4; i++) {
            int n = n0 + ty + 8*i;
            float v = sx[tx][ty + 8*i];
            __nv_bfloat16 hi = __float2bfloat16(v);
            __nv_bfloat16 lo = __float2bfloat16(v - __bfloat162float(hi));
            g_xt_hi[n*256 + c0 + tx] = hi;
            g_xt_lo[n*256 + c0 + tx] = lo;
        }
    }
}

// ---------------- K1: hedgehog GEMM via mma.sync bf16, cp.async 2-stage ------
#define APITCH 24
__global__ void __launch_bounds__(256, 2)
k1mma(const float* __restrict__ bmq, const float* __restrict__ bmk) {
    __shared__ __nv_bfloat16 Ah[2][128][APITCH], Al[2][128][APITCH];
    __shared__ __nv_bfloat16 Bh[2][64][APITCH],  Bl[2][64][APITCH];

    int t = threadIdx.x;           // 256
    int lane = t & 31, wid = t >> 5;
    int wm = wid >> 1, wn = wid & 1;
    int m0 = blockIdx.x * 128;     // 2 M-tiles
    int n0 = blockIdx.y * 64;      // 64 N-tiles
    int z  = blockIdx.z;           // q / k
    const __nv_bfloat16* gAh = z ? g_wk_hi : g_wq_hi;
    const __nv_bfloat16* gAl = z ? g_wk_lo : g_wq_lo;
    const float* bm = z ? bmk : bmq;
    float* f        = z ? g_kf : g_qf;

    float acc[2][4][4] = {};       // [mtile][ntile][reg]

    int a_row = (lane & 15), a_col = (lane >> 4) * 8;
    int b_row = (lane >> 4) * 8 + (lane & 7), b_col = ((lane >> 3) & 1) * 8;

    int r  = t >> 1, cc = (t & 1) * 8;          // A: 128 rows x 16 cols
    int rb = (t < 128) ? r : 0;                 // clamp: B pointers stay in-bounds
    const __nv_bfloat16* pAh = &gAh[(m0 + r)*256 + cc];
    const __nv_bfloat16* pAl = &gAl[(m0 + r)*256 + cc];
    const __nv_bfloat16* pBh = &g_xt_hi[(n0 + rb)*256 + cc];
    const __nv_bfloat16* pBl = &g_xt_lo[(n0 + rb)*256 + cc];

    {   // prefetch stage 0
        cp16(smem_u32(&Ah[0][r][cc]), pAh);
        cp16(smem_u32(&Al[0][r][cc]), pAl);
        if (t < 128) {
            cp16(smem_u32(&Bh[0][rb][cc]), pBh);
            cp16(smem_u32(&Bl[0][rb][cc]), pBl);
        }
        CP_COMMIT();
    }

    for (int ks = 0; ks < 16; ks++) {
        if (ks < 15) {
            int s = (ks + 1) & 1, k0 = (ks + 1) * 16;
            cp16(smem_u32(&Ah[s][r][cc]), pAh + k0);
            cp16(smem_u32(&Al[s][r][cc]), pAl + k0);
            if (t < 128) {
                cp16(smem_u32(&Bh[s][rb][cc]), pBh + k0);
                cp16(smem_u32(&Bl[s][rb][cc]), pBl + k0);
            }
            CP_COMMIT();
            CP_WAIT1();
        } else {
            CP_WAIT0();
        }
        __syncthreads();
        int s = ks & 1;

        uint32_t ah[2][4], al[2][4], bh[4][2], bl[4][2];
        #pragma unroll
        for (int mt = 0; mt < 2; mt++) {
            uint32_t ad = smem_u32(&Ah[s][wm*32 + mt*16 + a_row][a_col]);
            ldm_x4(ad, ah[mt][0], ah[mt][1], ah[mt][2], ah[mt][3]);
            uint32_t ad2 = smem_u32(&Al[s][wm*32 + mt*16 + a_row][a_col]);
            ldm_x4(ad2, al[mt][0], al[mt][1], al[mt][2], al[mt][3]);
        }
        #pragma unroll
        for (int np = 0; np < 2; np++) {
            uint32_t bd = smem_u32(&Bh[s][wn*32 + np*16 + b_row][b_col]);
            ldm_x4(bd, bh[np*2][0], bh[np*2][1], bh[np*2+1][0], bh[np*2+1][1]);
            uint32_t bd2 = smem_u32(&Bl[s][wn*32 + np*16 + b_row][b_col]);
            ldm_x4(bd2, bl[np*2][0], bl[np*2][1], bl[np*2+1][0], bl[np*2+1][1]);
        }
        #pragma unroll
        for (int mt = 0; mt < 2; mt++)
            #pragma unroll
            for (int nt = 0; nt < 4; nt++) {
                mma_bf16(acc[mt][nt], ah[mt], bh[nt]);
                mma_bf16(acc[mt][nt], ah[mt], bl[nt]);
                mma_bf16(acc[mt][nt], al[mt], bh[nt]);
            }
        __syncthreads();
    }

    // epilogue: bias + exp(+h) only (negative heads are reciprocals, on the fly)
    int qr = lane >> 2, qc = (lane & 3) * 2;
    #pragma unroll
    for (int mt = 0; mt < 2; mt++) {
        int ob = m0 + wm*32 + mt*16;
        int o0 = ob + qr, o1 = ob + qr + 8;
        float b0 = bm[o0 & 63], b1 = bm[o1 & 63];
        #pragma unroll
        for (int nt = 0; nt < 4; nt++) {
            int n = n0 + wn*32 + nt*8 + qc;
            float h00 = acc[mt][nt][0] + b0, h01 = acc[mt][nt][1] + b0;
            float h10 = acc[mt][nt][2] + b1, h11 = acc[mt][nt][3] + b1;
            float2 p0 = {__expf(h00), __expf(h01)};
            float2 p1 = {__expf(h10), __expf(h11)};
            *(float2*)&f[(size_t)o0*N_TOK + n] = p0;
            *(float2*)&f[(size_t)o1*N_TOK + n] = p1;
        }
    }
}

// ---------------- K2a: depthwise 3x3x3 conv, plane-major, LDS-minimized ------
#define CV_PD 19
#define CV_PP 342          // 18*19 plane pitch
__global__ void __launch_bounds__(256) k_conv(const float* __restrict__ x,
                                              const float* __restrict__ Wv,
                                              const float* __restrict__ bv) {
    __shared__ float sx[6*CV_PP]; // 2052 floats
    __shared__ float sw[27];
    int c  = blockIdx.x;           // 256
    int hs = blockIdx.y;           // 4
    int t  = threadIdx.x;          // 256
    int ww = t >> 4, dd = t & 15;

    for (int i = t; i < 6*CV_PP; i += 256) sx[i] = 0.f;
    if (t < 27) sw[t] = Wv[c*27 + t];
    __syncthreads();
    #pragma unroll
    for (int p = 0; p < 6; p++) {
        int hz = hs*4 - 1 + p;
        if (hz >= 0 && hz < 16)
            sx[p*CV_PP + (ww+1)*CV_PD + dd + 1] = x[c*4096 + hz*256 + ww*16 + dd];
    }
    __syncthreads();

    float bias = bv[c];
    float acc[4] = {bias, bias, bias, bias};
    #pragma unroll
    for (int p = 0; p < 6; p++) {
        #pragma unroll
        for (int b = 0; b < 3; b++) {
            const float* row = &sx[p*CV_PP + (ww + b)*CV_PD + dd];
            float r0 = row[0], r1 = row[1], r2 = row[2];
            #pragma unroll
            for (int a = 0; a < 3; a++) {
                int hh = p - a;            // plane p feeds output row hh with tap a
                if (hh >= 0 && hh < 4)     // compile-time resolved
                    acc[hh] += sw[a*9 + b*3 + 0]*r0 + sw[a*9 + b*3 + 1]*r1
                             + sw[a*9 + b*3 + 2]*r2;
            }
        }
    }
    #pragma unroll
    for (int hh = 0; hh < 4; hh++)
        g_v[c*N_TOK + (hs*4 + hh)*256 + ww*16 + dd] = acc[hh];
}

// ---------------- K2b: per-head v mix + exp(+) (128 thr, 4x4, 32n tiles) -----
__global__ void __launch_bounds__(128) k_vmix(const float* __restrict__ Wmv,
                                              const float* __restrict__ bmv) {
    __shared__ float As[16][68];   // Wmv^T staged: [d][e]
    __shared__ float Bs[16][32];   // v: [d][n]
    int h  = blockIdx.x;           // 4
    int n0 = blockIdx.y * 32;      // 128 tiles
    int t  = threadIdx.x;          // 128
    int tx = t & 7, ty = t >> 3;   // 8(n) x 16(e)

    float acc[4][4] = {};

    for (int k0 = 0; k0 < 64; k0 += 16) {
        #pragma unroll
        for (int i = 0; i < 2; i++) {            // A: 64(e) x 16(d)
            int j = t + 128*i;
            int lm = j >> 2, lk = (j & 3) * 4;
            float4 av = *(const float4*)&Wmv[lm*64 + k0 + lk];
            As[lk+0][lm] = av.x; As[lk+1][lm] = av.y;
            As[lk+2][lm] = av.z; As[lk+3][lm] = av.w;
        }
        {                                         // B: 16(d) x 32(n)
            int bk = t >> 3, bn = (t & 7) * 4;
            *(float4*)&Bs[bk][bn] = *(const float4*)&g_v[(h*64 + k0 + bk)*N_TOK + n0 + bn];
        }
        __syncthreads();
        #pragma unroll
        for (int kk = 0; kk < 16; kk++) {
            float a[4], b[4];
            *(float4*)&a[0] = *(const float4*)&As[kk][ty*4];
            *(float4*)&b[0] = *(const float4*)&Bs[kk][tx*4];
            #pragma unroll
            for (int i = 0; i < 4; i++)
                #pragma unroll
                for (int j = 0; j < 4; j++)
                    acc[i][j] += a[i] * b[j];
        }
        __syncthreads();
    }

    int n = n0 + tx*4;
    #pragma unroll
    for (int i = 0; i < 4; i++) {
        int e = ty*4 + i;
        float bias = bmv[e];
        float h0 = acc[i][0] + bias, h1 = acc[i][1] + bias;
        float h2 = acc[i][2] + bias, h3 = acc[i][3] + bias;
        float4 p = {__expf(h0), __expf(h1), __expf(h2), __expf(h3)};
        *(float4*)&g_vf[(h*64 + e)*N_TOK + n] = p;
    }
}

// ---------------- K3b: partial KV + partial S (rcp for neg heads) ------------
__global__ void __launch_bounds__(128) k_pkv() {
    __shared__ float skt[16][68];  // kf transposed: [nn][e]
    __shared__ float svt[16][68];  // vf transposed: [nn][d]
    int h = blockIdx.x, chunk = blockIdx.y;
    int hb = h & 3;
    bool neg = h >= 4;
    int t = threadIdx.x;           // 128
    int tx = t & 15, ty = t >> 4;
    int base_n = chunk * 128;

    float acc[8][4] = {};
    float s[2] = {};

    for (int sub = 0; sub < 8; sub++) {
        int n0 = base_n + sub * 16;
        #pragma unroll
        for (int i = 0; i < 2; i++) {
            int j = t + 128*i;
            int e = j >> 2, nf = (j & 3) * 4;
            float4 kq = *(const float4*)&g_kf[(hb*64 + e)*N_TOK + n0 + nf];
            if (neg) kq = rcp4(kq);
            skt[nf+0][e] = kq.x; skt[nf+1][e] = kq.y;
            skt[nf+2][e] = kq.z; skt[nf+3][e] = kq.w;
            s[i] += (kq.x + kq.y) + (kq.z + kq.w);
            float4 vq = *(const float4*)&g_vf[(hb*64 + e)*N_TOK + n0 + nf];
            if (neg) vq = rcp4(vq);
            svt[nf+0][e] = vq.x; svt[nf+1][e] = vq.y;
            svt[nf+2][e] = vq.z; svt[nf+3][e] = vq.w;
        }
        __syncthreads();
        #pragma unroll
        for (int nn = 0; nn < 16; nn++) {
            float a[8], b[4];
            *(float4*)&a[0] = *(const float4*)&skt[nn][ty*8];
            *(float4*)&a[4] = *(const float4*)&skt[nn][ty*8 + 4];
            *(float4*)&b[0] = *(const float4*)&svt[nn][tx*4];
            #pragma unroll
            for (int i = 0; i < 8; i++)
                #pragma unroll
                for (int j = 0; j < 4; j++)
                    acc[i][j] += a[i] * b[j];
        }
        __syncthreads();
    }

    float* dst = &g_pKV[(h*NCHUNK + chunk)*64*64];
    #pragma unroll
    for (int i = 0; i < 8; i++) {
        float4 c0 = {acc[i][0], acc[i][1], acc[i][2], acc[i][3]};
        *(float4*)&dst[(ty*8 + i)*64 + tx*4] = c0;
    }

    #pragma unroll
    for (int i = 0; i < 2; i++) {
        s[i] += __shfl_down_sync(0xffffffffu, s[i], 2);
        s[i] += __shfl_down_sync(0xffffffffu, s[i], 1);
    }
    if ((t & 3) == 0) {
        g_pS[(h*NCHUNK + chunk)*64 + (t >> 2)]      = s[0];
        g_pS[(h*NCHUNK + chunk)*64 + (t >> 2) + 32] = s[1];
    }
}

// ---------------- K3c: reduce partial KV and partial S (128 blocks) ----------
__global__ void __launch_bounds__(256) k_rkv() {
    int h = blockIdx.x;            // 8
    int sl = blockIdx.y;           // 16 slices of 256 idx
    int t = threadIdx.x;           // 256
    int idx = sl * 256 + t;
    float acc = 0.f;
    #pragma unroll
    for (int c = 0; c < NCHUNK; c++)
        acc += g_pKV[(h*NCHUNK + c)*4096 + idx];
    g_KV[h*4096 + idx] = acc;
    if (sl == 0 && t < 64) {
        float sa = 0.f;
        #pragma unroll
        for (int c = 0; c < NCHUNK; c++)
            sa += g_pS[(h*NCHUNK + c)*64 + t];
        g_S[h*64 + t] = sa;
    }
}

// ---------------- K4: out = (qf . KV) / (qf . S + eps) (128 thr, 8x4) --------
__global__ void __launch_bounds__(128) k_out(float* __restrict__ out) {
    __shared__ float sKV[64][68];  // [e][d]
    __shared__ float Bs[16][64];   // qf: [e][n]
    __shared__ float sS[64];
    int h  = blockIdx.x;           // 8
    int hb = h & 3;
    bool neg = h >= 4;
    int n0 = blockIdx.y * 64;      // 64 tiles
    int t  = threadIdx.x;          // 128
    int tx = t & 15, ty = t >> 4;

    #pragma unroll
    for (int i = 0; i < 8; i++) {
        int j = t + 128*i;
        int e = j >> 4, dc = (j & 15) * 4;
        *(float4*)&sKV[e][dc] = *(const float4*)&g_KV[h*4096 + e*64 + dc];
    }
    if (t < 64) sS[t] = g_S[h*64 + t];

    float acc[8][4] = {};
    float dacc[4] = {};

    for (int k0 = 0; k0 < 64; k0 += 16) {
        #pragma unroll
        for (int i = 0; i < 2; i++) {
            int j = t + 128*i;
            int bk = j >> 4, bn = (j & 15) * 4;
            float4 qv = *(const float4*)&g_qf[(hb*64 + k0 + bk)*N_TOK + n0 + bn];
            if (neg) qv = rcp4(qv);
            *(float4*)&Bs[bk][bn] = qv;
        }
        __syncthreads();
        #pragma unroll
        for (int kk = 0; kk < 16; kk++) {
            int e = k0 + kk;
            float a[8], b[4];
            *(float4*)&a[0] = *(const float4*)&sKV[e][ty*8];
            *(float4*)&a[4] = *(const float4*)&sKV[e][ty*8 + 4];
            *(float4*)&b[0] = *(const float4*)&Bs[kk][tx*4];
            float sv = sS[e];
            #pragma unroll
            for (int j = 0; j < 4; j++) dacc[j] += sv * b[j];
            #pragma unroll
            for (int i = 0; i < 8; i++)
                #pragma unroll
                for (int j = 0; j < 4; j++)
                    acc[i][j] += a[i] * b[j];
        }
        __syncthreads();
    }

    float inv[4];
    #pragma unroll
    for (int j = 0; j < 4; j++) inv[j] = 1.f / (dacc[j] + HEPS);

    int n = n0 + tx*4;
    #pragma unroll
    for (int i = 0; i < 8; i++) {
        int d = ty*8 + i;
        float4 c0 = {acc[i][0]*inv[0], acc[i][1]*inv[1], acc[i][2]*inv[2], acc[i][3]*inv[3]};
        *(float4*)&out[(h*64 + d)*N_TOK + n] = c0;
    }
}

// -----------------------------------------------------------------------------
extern "C" void kernel_launch(void* const* d_in, const int* in_sizes, int n_in,
                              void* d_out, int out_size) {
    const float* x   = (const float*)d_in[0];   // [1,256,16,16,16]
    const float* Wq  = (const float*)d_in[1];   // [256,256]
    const float* Wk  = (const float*)d_in[2];   // [256,256]
    const float* Wv  = (const float*)d_in[3];   // [256,1,3,3,3]
    const float* bv  = (const float*)d_in[4];   // [256]
    const float* Wmq = (const float*)d_in[5];   // [64,64]
    const float* bmq = (const float*)d_in[6];   // [64]
    const float* Wmk = (const float*)d_in[7];   // [64,64]
    const float* bmk = (const float*)d_in[8];   // [64]
    const float* Wmv = (const float*)d_in[9];   // [64,64]
    const float* bmv = (const float*)d_in[10];  // [64]
    float* out = (float*)d_out;                 // [1,512,16,16,16]

    k_prep <<<1536,                256>>>(Wq, Wk, Wmq, Wmk, x);
    k1mma  <<<dim3(2, 64, 2),      256>>>(bmq, bmk);
    k_conv <<<dim3(256, 4),        256>>>(x, Wv, bv);
    k_vmix <<<dim3(4, 128),        128>>>(Wmv, bmv);
    k_pkv  <<<dim3(8, NCHUNK),     128>>>();
    k_rkv  <<<dim3(8, 16),         256>>>();
    k_out  <<<dim3(8, 64),         128>>>(out);
}